// round 14
// baseline (speedup 1.0000x reference)
#include <cuda_runtime.h>
#include <cuda_bf16.h>
#include <cstdint>

#define BB 4
#define TT 2048
#define CC 256
#define HH 8
#define DH 32
#define QR 32
#define KVR 64
#define NTOK (BB*TT)          // 8192
#define TOKTILE 16
#define NBLK (NTOK/TOKTILE)   // 512

// ---------------- scratch (device globals; no allocation allowed) ----------------
__device__ __nv_bfloat16 g_qb[(size_t)BB*HH*TT*DH];      // [bh][t][d], pre-scaled
__device__ __nv_bfloat16 g_kb[(size_t)BB*HH*TT*DH];      // [bh][t][d]
__device__ __nv_bfloat16 g_vT[(size_t)BB*HH*DH*TT];      // [bh][d][t]  (transposed)
__device__ unsigned g_yb[(size_t)NTOK*CC/2];             // attention out, bf16 pairs [tok][c/2]
__device__ unsigned g_owb[(size_t)256*128];              // o_w bf16 pairs [d][c2]
__device__ ulonglong2 g_wAT4[(size_t)64*96];             // down-proj W^T packed [c4][r]
__device__ unsigned g_wub[(size_t)768*32];               // up-proj weights bf16 pairs [n][r/2]

typedef unsigned long long u64;

// ---------------- packed f32x2 helpers ----------------
__device__ __forceinline__ u64 pack2(float lo, float hi) {
    u64 r; asm("mov.b64 %0, {%1, %2};" : "=l"(r) : "f"(lo), "f"(hi)); return r;
}
__device__ __forceinline__ float2 unpack2(u64 v) {
    float2 r; asm("mov.b64 {%0, %1}, %2;" : "=f"(r.x), "=f"(r.y) : "l"(v)); return r;
}
__device__ __forceinline__ u64 fma2(u64 a, u64 b, u64 c) {
    u64 d; asm("fma.rn.f32x2 %0, %1, %2, %3;" : "=l"(d) : "l"(a), "l"(b), "l"(c)); return d;
}

// ---------------- bf16 helpers ----------------
__device__ __forceinline__ unsigned bf16x2(float lo, float hi) {
    unsigned r; asm("cvt.rn.bf16x2.f32 %0, %1, %2;" : "=r"(r) : "f"(hi), "f"(lo)); return r;
}
__device__ __forceinline__ void mma_bf16(float* d,
    unsigned a0, unsigned a1, unsigned a2, unsigned a3, unsigned b0, unsigned b1) {
    asm volatile("mma.sync.aligned.m16n8k16.row.col.f32.bf16.bf16.f32 "
        "{%0,%1,%2,%3}, {%4,%5,%6,%7}, {%8,%9}, {%0,%1,%2,%3};"
        : "+f"(d[0]), "+f"(d[1]), "+f"(d[2]), "+f"(d[3])
        : "r"(a0), "r"(a1), "r"(a2), "r"(a3), "r"(b0), "r"(b1));
}

// ============================================================================
// k0: one-time weight repack/transpose.
// ============================================================================
__global__ void __launch_bounds__(256) k0_prep(
    const float* __restrict__ o_w,
    const float* __restrict__ q_a_w, const float* __restrict__ kv_a_w,
    const float* __restrict__ q_b_w, const float* __restrict__ k_w,
    const float* __restrict__ v_w)
{
    int i = blockIdx.x * 256 + threadIdx.x;
    if (i < 32768) {
        int d = i >> 7, c2 = i & 127;
        g_owb[(size_t)d*128 + c2] = bf16x2(o_w[(size_t)d*256 + 2*c2],
                                           o_w[(size_t)d*256 + 2*c2 + 1]);
    } else if (i < 38912) {
        int j = i - 32768;
        int c4 = j / 96, r = j % 96;
        const float* src = (r < QR) ? (q_a_w + (size_t)r*CC)
                                    : (kv_a_w + (size_t)(r-QR)*CC);
        ulonglong2 v;
        v.x = pack2(src[4*c4],     src[4*c4 + 1]);
        v.y = pack2(src[4*c4 + 2], src[4*c4 + 3]);
        g_wAT4[(size_t)c4*96 + r] = v;
    } else if (i < 63488) {
        int j = i - 38912;            // 0..24575
        int n = j >> 5, cx = j & 31;  // cx = rank-pair index
        float lo = 0.f, hi = 0.f;
        if (n < 256) {
            if (cx < 16) { lo = q_b_w[(size_t)n*QR + 2*cx]; hi = q_b_w[(size_t)n*QR + 2*cx + 1]; }
        } else if (n < 512) {
            lo = k_w[(size_t)(n-256)*KVR + 2*cx]; hi = k_w[(size_t)(n-256)*KVR + 2*cx + 1];
        } else {
            lo = v_w[(size_t)(n-512)*KVR + 2*cx]; hi = v_w[(size_t)(n-512)*KVR + 2*cx + 1];
        }
        g_wub[(size_t)n*32 + cx] = bf16x2(lo, hi);
    }
}

// ============================================================================
// k1: FUSED LayerNorm + down-proj (fp32 fma2) + up-proj (bf16 TENSOR MMA).
// lat kept in smem as bf16 A-fragment layout. v transposed via smem.
// ============================================================================
__global__ void __launch_bounds__(256) k1_fused(
    const float* __restrict__ x, const float* __restrict__ norm_w,
    const float* __restrict__ q_bias, const float* __restrict__ kv_bias)
{
    __shared__ __align__(16) float xs[TOKTILE][CC];
    __shared__ __align__(16) __nv_bfloat16 latb[16*104];   // [t][r], stride 104
    __shared__ __align__(16) __nv_bfloat16 vsb[16*264];    // [t][c], stride 264
    const int tok0 = blockIdx.x * TOKTILE;
    const int tid = threadIdx.x;

    const float4* xsrc = (const float4*)(x + (size_t)tok0 * CC);
    float4* xd = (float4*)xs;
#pragma unroll
    for (int i = 0; i < 4; i++) xd[tid + i*256] = xsrc[tid + i*256];
    __syncthreads();

    // LayerNorm
    const int w = tid >> 5, l = tid & 31;
    for (int t = w; t < TOKTILE; t += 8) {
        float s = 0.f, sq = 0.f;
#pragma unroll
        for (int i = 0; i < 8; i++) { float v = xs[t][l + 32*i]; s += v; sq += v*v; }
#pragma unroll
        for (int o = 16; o; o >>= 1) {
            s  += __shfl_xor_sync(0xffffffffu, s,  o);
            sq += __shfl_xor_sync(0xffffffffu, sq, o);
        }
        float mean = s * (1.f/CC);
        float var  = sq * (1.f/CC) - mean*mean;
        float rstd = 1.f / sqrtf(var + 1e-5f);
#pragma unroll
        for (int i = 0; i < 8; i++) {
            int c = l + 32*i;
            xs[t][c] = (xs[t][c] - mean) * rstd * norm_w[c];
        }
    }
    __syncthreads();

    // down-proj: 192 threads, thread = (r, token-half); write lat bf16 [t][r]
    if (tid < 192) {
        const int r = tid % 96, th = tid / 96;
        const int t0 = th * 8;
        u64 acc[8];
#pragma unroll
        for (int tt = 0; tt < 8; tt++) acc[tt] = 0ull;
#pragma unroll 8
        for (int c4 = 0; c4 < 64; c4++) {
            ulonglong2 w4 = g_wAT4[(size_t)c4*96 + r];
#pragma unroll
            for (int tt = 0; tt < 8; tt++) {
                ulonglong2 xv = *(const ulonglong2*)&xs[t0 + tt][4*c4];
                acc[tt] = fma2(xv.x, w4.x, acc[tt]);
                acc[tt] = fma2(xv.y, w4.y, acc[tt]);
            }
        }
        const float bias = (r < QR) ? q_bias[r] : kv_bias[r - QR];
#pragma unroll
        for (int tt = 0; tt < 8; tt++) {
            float2 a = unpack2(acc[tt]);
            latb[(t0 + tt)*104 + r] = __float2bfloat16_rn(a.x + a.y + bias);
        }
    }
    __syncthreads();

    // up-proj on tensor cores: A = lat[16 x 96] bf16, B = g_wub rows.
    const int lane = tid & 31, gid = lane >> 2, tig = lane & 3;
    const float SC = 0.17677669529663687f * 1.4426950408889634f; // 1/sqrt(32)*log2(e)

    unsigned aA[6][4];
    const unsigned* latu = (const unsigned*)latb;
#pragma unroll
    for (int kg = 0; kg < 6; kg++) {
        aA[kg][0] = latu[gid*52 + 8*kg + tig];
        aA[kg][1] = latu[(gid+8)*52 + 8*kg + tig];
        aA[kg][2] = latu[gid*52 + 8*kg + tig + 4];
        aA[kg][3] = latu[(gid+8)*52 + 8*kg + tig + 4];
    }

    const int b = tok0 / TT;
    const int tA = (tok0 % TT) + gid;    // token row gid within batch
    unsigned* gq_u = (unsigned*)g_qb;
    unsigned* gk_u = (unsigned*)g_kb;
    unsigned* vs_u = (unsigned*)vsb;

#pragma unroll
    for (int j = 0; j < 12; j++) {
        const int nc = w + 8*j;
        const int row = 8*nc + gid;
        float acc[4] = {0.f, 0.f, 0.f, 0.f};
        if (nc < 32) {
#pragma unroll
            for (int kk = 0; kk < 2; kk++) {
                unsigned b0 = g_wub[(size_t)row*32 + 8*kk + tig];
                unsigned b1 = g_wub[(size_t)row*32 + 8*kk + tig + 4];
                mma_bf16(acc, aA[kk][0], aA[kk][1], aA[kk][2], aA[kk][3], b0, b1);
            }
            int h = nc >> 2, d2 = 4*(nc & 3) + tig;
            size_t base = ((size_t)(b*HH + h)*TT + tA)*16 + d2;
            gq_u[base]       = bf16x2(acc[0]*SC, acc[1]*SC);
            gq_u[base + 128] = bf16x2(acc[2]*SC, acc[3]*SC);
        } else {
#pragma unroll
            for (int kk = 0; kk < 4; kk++) {
                unsigned b0 = g_wub[(size_t)row*32 + 8*kk + tig];
                unsigned b1 = g_wub[(size_t)row*32 + 8*kk + tig + 4];
                mma_bf16(acc, aA[2+kk][0], aA[2+kk][1], aA[2+kk][2], aA[2+kk][3], b0, b1);
            }
            if (nc < 64) {
                int ncl = nc - 32;
                int h = ncl >> 2, d2 = 4*(ncl & 3) + tig;
                size_t base = ((size_t)(b*HH + h)*TT + tA)*16 + d2;
                gk_u[base]       = bf16x2(acc[0], acc[1]);
                gk_u[base + 128] = bf16x2(acc[2], acc[3]);
            } else {
                int c2 = 4*(nc - 64) + tig;     // (8*(nc-64)+2*tig)/2
                vs_u[gid*132 + c2]     = bf16x2(acc[0], acc[1]);
                vs_u[(gid+8)*132 + c2] = bf16x2(acc[2], acc[3]);
            }
        }
    }
    __syncthreads();

    // v transpose store: thread = output channel c
    {
        const int c = tid, h = c >> 5, d = c & 31;
        const unsigned short* vh = (const unsigned short*)vsb;
        unsigned* vt_u = (unsigned*)g_vT + (((size_t)(b*HH + h)*DH + d)*TT + (tok0 % TT))/2;
#pragma unroll
        for (int p = 0; p < 8; p++) {
            unsigned lo = vh[(2*p)*264 + c];
            unsigned hi = vh[(2*p+1)*264 + c];
            vt_u[p] = lo | (hi << 16);
        }
    }
}

// ============================================================================
// k3: flash attention, bf16 m16n8k16, fixed-max softmax, register-resident P.
// ============================================================================
#define KB_STR 40
#define VB_STR 72
__global__ void __launch_bounds__(128, 3) k3_attn_mma()
{
    __shared__ __align__(16) __nv_bfloat16 Kbs[64*KB_STR];   // [key][dim]
    __shared__ __align__(16) __nv_bfloat16 Vbs[32*VB_STR];   // [dim][key]

    const int tid = threadIdx.x;
    const int w = tid >> 5, lane = tid & 31;
    const int gid = lane >> 2, tig = lane & 3;
    const int bh = blockIdx.y;
    const int qbase = blockIdx.x * 128 + w * 32;

    const __nv_bfloat16* qptr = g_qb + (size_t)bh*TT*DH;
    unsigned qA[2][2][4];
#pragma unroll
    for (int mh = 0; mh < 2; mh++) {
        const int rA = qbase + 16*mh + gid, rB = rA + 8;
#pragma unroll
        for (int kg = 0; kg < 2; kg++) {
            qA[mh][kg][0] = *(const unsigned*)(qptr + (size_t)rA*DH + 16*kg + 2*tig);
            qA[mh][kg][1] = *(const unsigned*)(qptr + (size_t)rB*DH + 16*kg + 2*tig);
            qA[mh][kg][2] = *(const unsigned*)(qptr + (size_t)rA*DH + 16*kg + 2*tig + 8);
            qA[mh][kg][3] = *(const unsigned*)(qptr + (size_t)rB*DH + 16*kg + 2*tig + 8);
        }
    }

    float y[2][4][4];
#pragma unroll
    for (int mh = 0; mh < 2; mh++)
#pragma unroll
        for (int i = 0; i < 4; i++)
#pragma unroll
            for (int j = 0; j < 4; j++) y[mh][i][j] = 0.f;
    float psA[2] = {0.f, 0.f}, psB[2] = {0.f, 0.f};

    const uint2* kg2 = (const uint2*)(g_kb + (size_t)bh*TT*DH);
    const uint2* vg2 = (const uint2*)(g_vT + (size_t)bh*DH*TT);

    for (int kt = 0; kt < TT; kt += 64) {
        __syncthreads();
#pragma unroll
        for (int i = 0; i < 4; i++) {
            int idx = tid + 128*i;
            int row = idx >> 3, c = idx & 7;
            *(uint2*)(Kbs + row*KB_STR + c*4) = kg2[(size_t)(kt + row)*8 + c];
        }
#pragma unroll
        for (int i = 0; i < 4; i++) {
            int idx = tid + 128*i;
            int row = idx >> 4, c = idx & 15;
            *(uint2*)(Vbs + row*VB_STR + c*4) = vg2[(size_t)row*(TT/4) + kt/4 + c];
        }
        __syncthreads();

#pragma unroll
        for (int sub = 0; sub < 2; sub++) {
            const int kb0 = 32*sub;

            float s[2][4][4];
#pragma unroll
            for (int nc = 0; nc < 4; nc++) {
                s[0][nc][0] = s[0][nc][1] = s[0][nc][2] = s[0][nc][3] = 0.f;
                s[1][nc][0] = s[1][nc][1] = s[1][nc][2] = s[1][nc][3] = 0.f;
#pragma unroll
                for (int kg = 0; kg < 2; kg++) {
                    const __nv_bfloat16* kr = Kbs + (kb0 + 8*nc + gid)*KB_STR + 16*kg + 2*tig;
                    unsigned b0 = *(const unsigned*)(kr);
                    unsigned b1 = *(const unsigned*)(kr + 8);
                    mma_bf16(s[0][nc], qA[0][kg][0], qA[0][kg][1], qA[0][kg][2], qA[0][kg][3], b0, b1);
                    mma_bf16(s[1][nc], qA[1][kg][0], qA[1][kg][1], qA[1][kg][2], qA[1][kg][3], b0, b1);
                }
            }

            unsigned pa[2][2][4];
#pragma unroll
            for (int mh = 0; mh < 2; mh++) {
#pragma unroll
                for (int kg = 0; kg < 2; kg++) {
                    float p00 = exp2f(s[mh][2*kg][0]);
                    float p01 = exp2f(s[mh][2*kg][1]);
                    float p02 = exp2f(s[mh][2*kg][2]);
                    float p03 = exp2f(s[mh][2*kg][3]);
                    float p10 = exp2f(s[mh][2*kg+1][0]);
                    float p11 = exp2f(s[mh][2*kg+1][1]);
                    float p12 = exp2f(s[mh][2*kg+1][2]);
                    float p13 = exp2f(s[mh][2*kg+1][3]);
                    psA[mh] += (p00 + p01) + (p10 + p11);
                    psB[mh] += (p02 + p03) + (p12 + p13);
                    pa[mh][kg][0] = bf16x2(p00, p01);
                    pa[mh][kg][1] = bf16x2(p02, p03);
                    pa[mh][kg][2] = bf16x2(p10, p11);
                    pa[mh][kg][3] = bf16x2(p12, p13);
                }
            }

#pragma unroll
            for (int kg = 0; kg < 2; kg++) {
#pragma unroll
                for (int nc2 = 0; nc2 < 4; nc2++) {
                    const __nv_bfloat16* vr = Vbs + (8*nc2 + gid)*VB_STR + kb0 + 16*kg + 2*tig;
                    unsigned b0 = *(const unsigned*)(vr);
                    unsigned b1 = *(const unsigned*)(vr + 8);
                    mma_bf16(y[0][nc2], pa[0][kg][0], pa[0][kg][1], pa[0][kg][2], pa[0][kg][3], b0, b1);
                    mma_bf16(y[1][nc2], pa[1][kg][0], pa[1][kg][1], pa[1][kg][2], pa[1][kg][3], b0, b1);
                }
            }
        }
    }

    const int b = bh >> 3, h = bh & 7;
#pragma unroll
    for (int mh = 0; mh < 2; mh++) {
        float sA = psA[mh], sB = psB[mh];
        sA += __shfl_xor_sync(0xffffffffu, sA, 1);
        sA += __shfl_xor_sync(0xffffffffu, sA, 2);
        sB += __shfl_xor_sync(0xffffffffu, sB, 1);
        sB += __shfl_xor_sync(0xffffffffu, sB, 2);
        const float inv0 = 1.0f / sA, inv1 = 1.0f / sB;
        const int rA = qbase + 16*mh + gid, rB = rA + 8;
#pragma unroll
        for (int nc2 = 0; nc2 < 4; nc2++) {
            int col = h*DH + nc2*8 + 2*tig;
            g_yb[((size_t)(b*TT + rA)*CC + col) >> 1] = bf16x2(y[mh][nc2][0]*inv0, y[mh][nc2][1]*inv0);
            g_yb[((size_t)(b*TT + rB)*CC + col) >> 1] = bf16x2(y[mh][nc2][2]*inv1, y[mh][nc2][3]*inv1);
        }
    }
}

// ============================================================================
// k4: output projection, bf16 MMA with SMEM-STAGED weights.
// CTA = 64 tokens x 64 out-cols; 256 threads (8 warps, warp w -> nc=w).
// ============================================================================
#define K4_SMEM (2*64*132*4)   // ws + ys, uint stride 132 per row
__global__ void __launch_bounds__(256) k4_oproj(
    const float* __restrict__ x, const float* __restrict__ gamma,
    float* __restrict__ out)
{
    extern __shared__ __align__(16) unsigned k4s[];
    unsigned* ws = k4s;              // [64][132] bf16 pairs: weight rows n_local
    unsigned* ys = k4s + 64*132;     // [64][132] bf16 pairs: y rows t_local
    const int tid = threadIdx.x;
    const int w = tid >> 5, lane = tid & 31;
    const int gid = lane >> 2, tig = lane & 3;
    const int tok0 = blockIdx.x * 64;
    const int cg = blockIdx.y;       // 0..3

    // stage weights + y (uint4, conflict-free: 132 = 33 uint4)
    {
        const uint4* wsrc = (const uint4*)(g_owb + (size_t)(cg*64)*128);
        const uint4* ysrc = (const uint4*)(g_yb + (size_t)tok0*128);
        uint4* ws4 = (uint4*)ws;
        uint4* ys4 = (uint4*)ys;
#pragma unroll
        for (int i = 0; i < 8; i++) {
            int idx = tid + 256*i;
            int r = idx >> 5, c4 = idx & 31;
            ws4[r*33 + c4] = wsrc[r*32 + c4];
            ys4[r*33 + c4] = ysrc[r*32 + c4];
        }
    }
    __syncthreads();

    const __nv_bfloat16* wsh = (const __nv_bfloat16*)ws;
    const __nv_bfloat16* ysh = (const __nv_bfloat16*)ys;

    float acc[4][4];
#pragma unroll
    for (int m = 0; m < 4; m++)
#pragma unroll
        for (int j = 0; j < 4; j++) acc[m][j] = 0.f;

#pragma unroll 4
    for (int kg = 0; kg < 16; kg++) {
        const __nv_bfloat16* wr = wsh + (8*w + gid)*264 + 16*kg + 2*tig;
        unsigned b0 = *(const unsigned*)(wr);
        unsigned b1 = *(const unsigned*)(wr + 8);
#pragma unroll
        for (int m = 0; m < 4; m++) {
            const __nv_bfloat16* yr = ysh + (16*m + gid)*264 + 16*kg + 2*tig;
            unsigned a0 = *(const unsigned*)(yr);
            unsigned a1 = *(const unsigned*)(yr + 8*264);
            unsigned a2 = *(const unsigned*)(yr + 8);
            unsigned a3 = *(const unsigned*)(yr + 8*264 + 8);
            mma_bf16(acc[m], a0, a1, a2, a3, b0, b1);
        }
    }

    // epilogue: out = x + gamma * acc
    const int n = cg*64 + 8*w + 2*tig;
    const float g0 = gamma[n], g1 = gamma[n + 1];
#pragma unroll
    for (int m = 0; m < 4; m++) {
        int rA = tok0 + 16*m + gid, rB = rA + 8;
        float2 xA = *(const float2*)&x[(size_t)rA*CC + n];
        float2 xB = *(const float2*)&x[(size_t)rB*CC + n];
        float2 oA; oA.x = xA.x + g0*acc[m][0]; oA.y = xA.y + g1*acc[m][1];
        float2 oB; oB.x = xB.x + g0*acc[m][2]; oB.y = xB.y + g1*acc[m][3];
        *(float2*)&out[(size_t)rA*CC + n] = oA;
        *(float2*)&out[(size_t)rB*CC + n] = oB;
    }
}

// ============================================================================
extern "C" void kernel_launch(void* const* d_in, const int* in_sizes, int n_in,
                              void* d_out, int out_size)
{
    const float* x       = (const float*)d_in[0];
    const float* q_a_w   = (const float*)d_in[1];
    const float* q_bias  = (const float*)d_in[2];
    const float* q_b_w   = (const float*)d_in[3];
    const float* kv_a_w  = (const float*)d_in[4];
    const float* kv_bias = (const float*)d_in[5];
    const float* k_w     = (const float*)d_in[6];
    const float* v_w     = (const float*)d_in[7];
    const float* o_w     = (const float*)d_in[8];
    const float* norm_w  = (const float*)d_in[9];
    const float* gamma   = (const float*)d_in[10];
    float* out = (float*)d_out;

    cudaFuncSetAttribute(k4_oproj,
                         cudaFuncAttributeMaxDynamicSharedMemorySize, K4_SMEM);

    k0_prep<<<248, 256>>>(o_w, q_a_w, kv_a_w, q_b_w, k_w, v_w);
    k1_fused<<<NBLK, 256>>>(x, norm_w, q_bias, kv_bias);
    dim3 g3(TT/128, BB*HH);
    k3_attn_mma<<<g3, 128>>>();
    dim3 g4(NTOK/64, 4);
    k4_oproj<<<g4, 256, K4_SMEM>>>(x, gamma, out);
}

// round 15
// speedup vs baseline: 1.4839x; 1.4839x over previous
#include <cuda_runtime.h>
#include <cuda_bf16.h>
#include <cstdint>

#define BB 4
#define TT 2048
#define CC 256
#define HH 8
#define DH 32
#define QR 32
#define KVR 64
#define NTOK (BB*TT)          // 8192
#define TOKTILE 16
#define NBLK (NTOK/TOKTILE)   // 512

// ---------------- scratch (device globals; no allocation allowed) ----------------
__device__ __nv_bfloat16 g_qb[(size_t)BB*HH*TT*DH];      // [bh][t][d], pre-scaled
__device__ __nv_bfloat16 g_kb[(size_t)BB*HH*TT*DH];      // [bh][t][d]
__device__ __nv_bfloat16 g_vT[(size_t)BB*HH*DH*TT];      // [bh][d][t]  (transposed)
__device__ unsigned g_yb[(size_t)NTOK*CC/2];             // attention out, bf16 pairs [tok][c/2]
__device__ unsigned g_owb[(size_t)256*128];              // o_w bf16 pairs [d][c2]
__device__ ulonglong2 g_wAT4[(size_t)64*96];             // down-proj W^T packed [c4][r]
__device__ unsigned g_wub[(size_t)768*32];               // up-proj weights bf16 pairs [n][r/2]

typedef unsigned long long u64;

// ---------------- packed f32x2 helpers ----------------
__device__ __forceinline__ u64 pack2(float lo, float hi) {
    u64 r; asm("mov.b64 %0, {%1, %2};" : "=l"(r) : "f"(lo), "f"(hi)); return r;
}
__device__ __forceinline__ float2 unpack2(u64 v) {
    float2 r; asm("mov.b64 {%0, %1}, %2;" : "=f"(r.x), "=f"(r.y) : "l"(v)); return r;
}
__device__ __forceinline__ u64 fma2(u64 a, u64 b, u64 c) {
    u64 d; asm("fma.rn.f32x2 %0, %1, %2, %3;" : "=l"(d) : "l"(a), "l"(b), "l"(c)); return d;
}

// ---------------- bf16 helpers ----------------
__device__ __forceinline__ unsigned bf16x2(float lo, float hi) {
    unsigned r; asm("cvt.rn.bf16x2.f32 %0, %1, %2;" : "=r"(r) : "f"(hi), "f"(lo)); return r;
}
__device__ __forceinline__ void mma_bf16(float* d,
    unsigned a0, unsigned a1, unsigned a2, unsigned a3, unsigned b0, unsigned b1) {
    asm volatile("mma.sync.aligned.m16n8k16.row.col.f32.bf16.bf16.f32 "
        "{%0,%1,%2,%3}, {%4,%5,%6,%7}, {%8,%9}, {%0,%1,%2,%3};"
        : "+f"(d[0]), "+f"(d[1]), "+f"(d[2]), "+f"(d[3])
        : "r"(a0), "r"(a1), "r"(a2), "r"(a3), "r"(b0), "r"(b1));
}

// ============================================================================
// k0: one-time weight repack/transpose.
// ============================================================================
__global__ void __launch_bounds__(256) k0_prep(
    const float* __restrict__ o_w,
    const float* __restrict__ q_a_w, const float* __restrict__ kv_a_w,
    const float* __restrict__ q_b_w, const float* __restrict__ k_w,
    const float* __restrict__ v_w)
{
    int i = blockIdx.x * 256 + threadIdx.x;
    if (i < 32768) {
        int d = i >> 7, c2 = i & 127;
        g_owb[(size_t)d*128 + c2] = bf16x2(o_w[(size_t)d*256 + 2*c2],
                                           o_w[(size_t)d*256 + 2*c2 + 1]);
    } else if (i < 38912) {
        int j = i - 32768;
        int c4 = j / 96, r = j % 96;
        const float* src = (r < QR) ? (q_a_w + (size_t)r*CC)
                                    : (kv_a_w + (size_t)(r-QR)*CC);
        ulonglong2 v;
        v.x = pack2(src[4*c4],     src[4*c4 + 1]);
        v.y = pack2(src[4*c4 + 2], src[4*c4 + 3]);
        g_wAT4[(size_t)c4*96 + r] = v;
    } else if (i < 63488) {
        int j = i - 38912;            // 0..24575
        int n = j >> 5, cx = j & 31;  // cx = rank-pair index
        float lo = 0.f, hi = 0.f;
        if (n < 256) {
            if (cx < 16) { lo = q_b_w[(size_t)n*QR + 2*cx]; hi = q_b_w[(size_t)n*QR + 2*cx + 1]; }
        } else if (n < 512) {
            lo = k_w[(size_t)(n-256)*KVR + 2*cx]; hi = k_w[(size_t)(n-256)*KVR + 2*cx + 1];
        } else {
            lo = v_w[(size_t)(n-512)*KVR + 2*cx]; hi = v_w[(size_t)(n-512)*KVR + 2*cx + 1];
        }
        g_wub[(size_t)n*32 + cx] = bf16x2(lo, hi);
    }
}

// ============================================================================
// k1: FUSED LayerNorm + down-proj (fp32 fma2) + up-proj (bf16 TENSOR MMA).
// lat kept in smem as bf16 A-fragment layout. v transposed via smem.
// ============================================================================
__global__ void __launch_bounds__(256) k1_fused(
    const float* __restrict__ x, const float* __restrict__ norm_w,
    const float* __restrict__ q_bias, const float* __restrict__ kv_bias)
{
    __shared__ __align__(16) float xs[TOKTILE][CC];
    __shared__ __align__(16) __nv_bfloat16 latb[16*104];   // [t][r], stride 104
    __shared__ __align__(16) __nv_bfloat16 vsb[16*264];    // [t][c], stride 264
    const int tok0 = blockIdx.x * TOKTILE;
    const int tid = threadIdx.x;

    const float4* xsrc = (const float4*)(x + (size_t)tok0 * CC);
    float4* xd = (float4*)xs;
#pragma unroll
    for (int i = 0; i < 4; i++) xd[tid + i*256] = xsrc[tid + i*256];
    __syncthreads();

    // LayerNorm
    const int w = tid >> 5, l = tid & 31;
    for (int t = w; t < TOKTILE; t += 8) {
        float s = 0.f, sq = 0.f;
#pragma unroll
        for (int i = 0; i < 8; i++) { float v = xs[t][l + 32*i]; s += v; sq += v*v; }
#pragma unroll
        for (int o = 16; o; o >>= 1) {
            s  += __shfl_xor_sync(0xffffffffu, s,  o);
            sq += __shfl_xor_sync(0xffffffffu, sq, o);
        }
        float mean = s * (1.f/CC);
        float var  = sq * (1.f/CC) - mean*mean;
        float rstd = 1.f / sqrtf(var + 1e-5f);
#pragma unroll
        for (int i = 0; i < 8; i++) {
            int c = l + 32*i;
            xs[t][c] = (xs[t][c] - mean) * rstd * norm_w[c];
        }
    }
    __syncthreads();

    // down-proj: 192 threads, thread = (r, token-half); write lat bf16 [t][r]
    if (tid < 192) {
        const int r = tid % 96, th = tid / 96;
        const int t0 = th * 8;
        u64 acc[8];
#pragma unroll
        for (int tt = 0; tt < 8; tt++) acc[tt] = 0ull;
#pragma unroll 8
        for (int c4 = 0; c4 < 64; c4++) {
            ulonglong2 w4 = g_wAT4[(size_t)c4*96 + r];
#pragma unroll
            for (int tt = 0; tt < 8; tt++) {
                ulonglong2 xv = *(const ulonglong2*)&xs[t0 + tt][4*c4];
                acc[tt] = fma2(xv.x, w4.x, acc[tt]);
                acc[tt] = fma2(xv.y, w4.y, acc[tt]);
            }
        }
        const float bias = (r < QR) ? q_bias[r] : kv_bias[r - QR];
#pragma unroll
        for (int tt = 0; tt < 8; tt++) {
            float2 a = unpack2(acc[tt]);
            latb[(t0 + tt)*104 + r] = __float2bfloat16_rn(a.x + a.y + bias);
        }
    }
    __syncthreads();

    // up-proj on tensor cores: A = lat[16 x 96] bf16, B = g_wub rows.
    const int lane = tid & 31, gid = lane >> 2, tig = lane & 3;
    const float SC = 0.17677669529663687f * 1.4426950408889634f; // 1/sqrt(32)*log2(e)

    unsigned aA[6][4];
    const unsigned* latu = (const unsigned*)latb;
#pragma unroll
    for (int kg = 0; kg < 6; kg++) {
        aA[kg][0] = latu[gid*52 + 8*kg + tig];
        aA[kg][1] = latu[(gid+8)*52 + 8*kg + tig];
        aA[kg][2] = latu[gid*52 + 8*kg + tig + 4];
        aA[kg][3] = latu[(gid+8)*52 + 8*kg + tig + 4];
    }

    const int b = tok0 / TT;
    const int tA = (tok0 % TT) + gid;    // token row gid within batch
    unsigned* gq_u = (unsigned*)g_qb;
    unsigned* gk_u = (unsigned*)g_kb;
    unsigned* vs_u = (unsigned*)vsb;

#pragma unroll
    for (int j = 0; j < 12; j++) {
        const int nc = w + 8*j;
        const int row = 8*nc + gid;
        float acc[4] = {0.f, 0.f, 0.f, 0.f};
        if (nc < 32) {
#pragma unroll
            for (int kk = 0; kk < 2; kk++) {
                unsigned b0 = g_wub[(size_t)row*32 + 8*kk + tig];
                unsigned b1 = g_wub[(size_t)row*32 + 8*kk + tig + 4];
                mma_bf16(acc, aA[kk][0], aA[kk][1], aA[kk][2], aA[kk][3], b0, b1);
            }
            int h = nc >> 2, d2 = 4*(nc & 3) + tig;
            size_t base = ((size_t)(b*HH + h)*TT + tA)*16 + d2;
            gq_u[base]       = bf16x2(acc[0]*SC, acc[1]*SC);
            gq_u[base + 128] = bf16x2(acc[2]*SC, acc[3]*SC);
        } else {
#pragma unroll
            for (int kk = 0; kk < 4; kk++) {
                unsigned b0 = g_wub[(size_t)row*32 + 8*kk + tig];
                unsigned b1 = g_wub[(size_t)row*32 + 8*kk + tig + 4];
                mma_bf16(acc, aA[2+kk][0], aA[2+kk][1], aA[2+kk][2], aA[2+kk][3], b0, b1);
            }
            if (nc < 64) {
                int ncl = nc - 32;
                int h = ncl >> 2, d2 = 4*(ncl & 3) + tig;
                size_t base = ((size_t)(b*HH + h)*TT + tA)*16 + d2;
                gk_u[base]       = bf16x2(acc[0], acc[1]);
                gk_u[base + 128] = bf16x2(acc[2], acc[3]);
            } else {
                int c2 = 4*(nc - 64) + tig;     // (8*(nc-64)+2*tig)/2
                vs_u[gid*132 + c2]     = bf16x2(acc[0], acc[1]);
                vs_u[(gid+8)*132 + c2] = bf16x2(acc[2], acc[3]);
            }
        }
    }
    __syncthreads();

    // v transpose store: thread = output channel c
    {
        const int c = tid, h = c >> 5, d = c & 31;
        const unsigned short* vh = (const unsigned short*)vsb;
        unsigned* vt_u = (unsigned*)g_vT + (((size_t)(b*HH + h)*DH + d)*TT + (tok0 % TT))/2;
#pragma unroll
        for (int p = 0; p < 8; p++) {
            unsigned lo = vh[(2*p)*264 + c];
            unsigned hi = vh[(2*p+1)*264 + c];
            vt_u[p] = lo | (hi << 16);
        }
    }
}

// ============================================================================
// k3: flash attention, bf16 m16n8k16, fixed-max softmax, register-resident P,
// DOUBLE-BUFFERED K/V tiles (next tile's LDG/STS overlaps current compute;
// one __syncthreads per tile).
// ============================================================================
#define KB_STR 40
#define VB_STR 72
__global__ void __launch_bounds__(128, 3) k3_attn_mma()
{
    __shared__ __align__(16) __nv_bfloat16 Kbs[2][64*KB_STR];   // [buf][key][dim]
    __shared__ __align__(16) __nv_bfloat16 Vbs[2][32*VB_STR];   // [buf][dim][key]

    const int tid = threadIdx.x;
    const int w = tid >> 5, lane = tid & 31;
    const int gid = lane >> 2, tig = lane & 3;
    const int bh = blockIdx.y;
    const int qbase = blockIdx.x * 128 + w * 32;

    const __nv_bfloat16* qptr = g_qb + (size_t)bh*TT*DH;
    unsigned qA[2][2][4];
#pragma unroll
    for (int mh = 0; mh < 2; mh++) {
        const int rA = qbase + 16*mh + gid, rB = rA + 8;
#pragma unroll
        for (int kg = 0; kg < 2; kg++) {
            qA[mh][kg][0] = *(const unsigned*)(qptr + (size_t)rA*DH + 16*kg + 2*tig);
            qA[mh][kg][1] = *(const unsigned*)(qptr + (size_t)rB*DH + 16*kg + 2*tig);
            qA[mh][kg][2] = *(const unsigned*)(qptr + (size_t)rA*DH + 16*kg + 2*tig + 8);
            qA[mh][kg][3] = *(const unsigned*)(qptr + (size_t)rB*DH + 16*kg + 2*tig + 8);
        }
    }

    float y[2][4][4];
#pragma unroll
    for (int mh = 0; mh < 2; mh++)
#pragma unroll
        for (int i = 0; i < 4; i++)
#pragma unroll
            for (int j = 0; j < 4; j++) y[mh][i][j] = 0.f;
    float psA[2] = {0.f, 0.f}, psB[2] = {0.f, 0.f};

    const uint2* kg2 = (const uint2*)(g_kb + (size_t)bh*TT*DH);
    const uint2* vg2 = (const uint2*)(g_vT + (size_t)bh*DH*TT);

    // row/col decomposition for the cooperative tile loads
    const int krow = tid >> 3, kc = tid & 7;      // K: 16 rows per pass, 8 uint2 cols
    const int vrow = tid >> 4, vc = tid & 15;     // V: 8 rows per pass, 16 uint2 cols

    // prologue: load tile 0 into buffer 0
#pragma unroll
    for (int i = 0; i < 4; i++) {
        *(uint2*)(&Kbs[0][0] + (krow + 16*i)*KB_STR + kc*4) = kg2[(size_t)(krow + 16*i)*8 + kc];
        *(uint2*)(&Vbs[0][0] + (vrow + 8*i)*VB_STR + vc*4)  = vg2[(size_t)(vrow + 8*i)*(TT/4) + vc];
    }
    __syncthreads();

    for (int t = 0; t < TT/64; t++) {
        const int cur = t & 1;
        // prefetch next tile into the other buffer (overlaps with compute below)
        if (t + 1 < TT/64) {
            const int kt = (t + 1) * 64;
            __nv_bfloat16* kd = &Kbs[cur ^ 1][0];
            __nv_bfloat16* vd = &Vbs[cur ^ 1][0];
#pragma unroll
            for (int i = 0; i < 4; i++) {
                *(uint2*)(kd + (krow + 16*i)*KB_STR + kc*4) = kg2[(size_t)(kt + krow + 16*i)*8 + kc];
                *(uint2*)(vd + (vrow + 8*i)*VB_STR + vc*4)  = vg2[(size_t)(vrow + 8*i)*(TT/4) + kt/4 + vc];
            }
        }

        const __nv_bfloat16* Kc = &Kbs[cur][0];
        const __nv_bfloat16* Vc = &Vbs[cur][0];

#pragma unroll
        for (int sub = 0; sub < 2; sub++) {
            const int kb0 = 32*sub;

            float s[2][4][4];
#pragma unroll
            for (int nc = 0; nc < 4; nc++) {
                s[0][nc][0] = s[0][nc][1] = s[0][nc][2] = s[0][nc][3] = 0.f;
                s[1][nc][0] = s[1][nc][1] = s[1][nc][2] = s[1][nc][3] = 0.f;
#pragma unroll
                for (int kg = 0; kg < 2; kg++) {
                    const __nv_bfloat16* kr = Kc + (kb0 + 8*nc + gid)*KB_STR + 16*kg + 2*tig;
                    unsigned b0 = *(const unsigned*)(kr);
                    unsigned b1 = *(const unsigned*)(kr + 8);
                    mma_bf16(s[0][nc], qA[0][kg][0], qA[0][kg][1], qA[0][kg][2], qA[0][kg][3], b0, b1);
                    mma_bf16(s[1][nc], qA[1][kg][0], qA[1][kg][1], qA[1][kg][2], qA[1][kg][3], b0, b1);
                }
            }

            unsigned pa[2][2][4];
#pragma unroll
            for (int mh = 0; mh < 2; mh++) {
#pragma unroll
                for (int kg = 0; kg < 2; kg++) {
                    float p00 = exp2f(s[mh][2*kg][0]);
                    float p01 = exp2f(s[mh][2*kg][1]);
                    float p02 = exp2f(s[mh][2*kg][2]);
                    float p03 = exp2f(s[mh][2*kg][3]);
                    float p10 = exp2f(s[mh][2*kg+1][0]);
                    float p11 = exp2f(s[mh][2*kg+1][1]);
                    float p12 = exp2f(s[mh][2*kg+1][2]);
                    float p13 = exp2f(s[mh][2*kg+1][3]);
                    psA[mh] += (p00 + p01) + (p10 + p11);
                    psB[mh] += (p02 + p03) + (p12 + p13);
                    pa[mh][kg][0] = bf16x2(p00, p01);
                    pa[mh][kg][1] = bf16x2(p02, p03);
                    pa[mh][kg][2] = bf16x2(p10, p11);
                    pa[mh][kg][3] = bf16x2(p12, p13);
                }
            }

#pragma unroll
            for (int kg = 0; kg < 2; kg++) {
#pragma unroll
                for (int nc2 = 0; nc2 < 4; nc2++) {
                    const __nv_bfloat16* vr = Vc + (8*nc2 + gid)*VB_STR + kb0 + 16*kg + 2*tig;
                    unsigned b0 = *(const unsigned*)(vr);
                    unsigned b1 = *(const unsigned*)(vr + 8);
                    mma_bf16(y[0][nc2], pa[0][kg][0], pa[0][kg][1], pa[0][kg][2], pa[0][kg][3], b0, b1);
                    mma_bf16(y[1][nc2], pa[1][kg][0], pa[1][kg][1], pa[1][kg][2], pa[1][kg][3], b0, b1);
                }
            }
        }
        __syncthreads();   // next-buffer writes visible; current buffer free for t+2
    }

    const int b = bh >> 3, h = bh & 7;
#pragma unroll
    for (int mh = 0; mh < 2; mh++) {
        float sA = psA[mh], sB = psB[mh];
        sA += __shfl_xor_sync(0xffffffffu, sA, 1);
        sA += __shfl_xor_sync(0xffffffffu, sA, 2);
        sB += __shfl_xor_sync(0xffffffffu, sB, 1);
        sB += __shfl_xor_sync(0xffffffffu, sB, 2);
        const float inv0 = 1.0f / sA, inv1 = 1.0f / sB;
        const int rA = qbase + 16*mh + gid, rB = rA + 8;
#pragma unroll
        for (int nc2 = 0; nc2 < 4; nc2++) {
            int col = h*DH + nc2*8 + 2*tig;
            g_yb[((size_t)(b*TT + rA)*CC + col) >> 1] = bf16x2(y[mh][nc2][0]*inv0, y[mh][nc2][1]*inv0);
            g_yb[((size_t)(b*TT + rB)*CC + col) >> 1] = bf16x2(y[mh][nc2][2]*inv1, y[mh][nc2][3]*inv1);
        }
    }
}

// ============================================================================
// k4: output projection, bf16 MMA with SMEM-STAGED weights.
// CTA = 64 tokens x 64 out-cols; 256 threads (8 warps, warp w -> nc=w).
// ============================================================================
#define K4_SMEM (2*64*132*4)   // ws + ys, uint stride 132 per row
__global__ void __launch_bounds__(256) k4_oproj(
    const float* __restrict__ x, const float* __restrict__ gamma,
    float* __restrict__ out)
{
    extern __shared__ __align__(16) unsigned k4s[];
    unsigned* ws = k4s;              // [64][132] bf16 pairs: weight rows n_local
    unsigned* ys = k4s + 64*132;     // [64][132] bf16 pairs: y rows t_local
    const int tid = threadIdx.x;
    const int w = tid >> 5, lane = tid & 31;
    const int gid = lane >> 2, tig = lane & 3;
    const int tok0 = blockIdx.x * 64;
    const int cg = blockIdx.y;       // 0..3

    // stage weights + y (uint4, conflict-free: 132 = 33 uint4)
    {
        const uint4* wsrc = (const uint4*)(g_owb + (size_t)(cg*64)*128);
        const uint4* ysrc = (const uint4*)(g_yb + (size_t)tok0*128);
        uint4* ws4 = (uint4*)ws;
        uint4* ys4 = (uint4*)ys;
#pragma unroll
        for (int i = 0; i < 8; i++) {
            int idx = tid + 256*i;
            int r = idx >> 5, c4 = idx & 31;
            ws4[r*33 + c4] = wsrc[r*32 + c4];
            ys4[r*33 + c4] = ysrc[r*32 + c4];
        }
    }
    __syncthreads();

    const __nv_bfloat16* wsh = (const __nv_bfloat16*)ws;
    const __nv_bfloat16* ysh = (const __nv_bfloat16*)ys;

    float acc[4][4];
#pragma unroll
    for (int m = 0; m < 4; m++)
#pragma unroll
        for (int j = 0; j < 4; j++) acc[m][j] = 0.f;

#pragma unroll 4
    for (int kg = 0; kg < 16; kg++) {
        const __nv_bfloat16* wr = wsh + (8*w + gid)*264 + 16*kg + 2*tig;
        unsigned b0 = *(const unsigned*)(wr);
        unsigned b1 = *(const unsigned*)(wr + 8);
#pragma unroll
        for (int m = 0; m < 4; m++) {
            const __nv_bfloat16* yr = ysh + (16*m + gid)*264 + 16*kg + 2*tig;
            unsigned a0 = *(const unsigned*)(yr);
            unsigned a1 = *(const unsigned*)(yr + 8*264);
            unsigned a2 = *(const unsigned*)(yr + 8);
            unsigned a3 = *(const unsigned*)(yr + 8*264 + 8);
            mma_bf16(acc[m], a0, a1, a2, a3, b0, b1);
        }
    }

    // epilogue: out = x + gamma * acc
    const int n = cg*64 + 8*w + 2*tig;
    const float g0 = gamma[n], g1 = gamma[n + 1];
#pragma unroll
    for (int m = 0; m < 4; m++) {
        int rA = tok0 + 16*m + gid, rB = rA + 8;
        float2 xA = *(const float2*)&x[(size_t)rA*CC + n];
        float2 xB = *(const float2*)&x[(size_t)rB*CC + n];
        float2 oA; oA.x = xA.x + g0*acc[m][0]; oA.y = xA.y + g1*acc[m][1];
        float2 oB; oB.x = xB.x + g0*acc[m][2]; oB.y = xB.y + g1*acc[m][3];
        *(float2*)&out[(size_t)rA*CC + n] = oA;
        *(float2*)&out[(size_t)rB*CC + n] = oB;
    }
}

// ============================================================================
extern "C" void kernel_launch(void* const* d_in, const int* in_sizes, int n_in,
                              void* d_out, int out_size)
{
    const float* x       = (const float*)d_in[0];
    const float* q_a_w   = (const float*)d_in[1];
    const float* q_bias  = (const float*)d_in[2];
    const float* q_b_w   = (const float*)d_in[3];
    const float* kv_a_w  = (const float*)d_in[4];
    const float* kv_bias = (const float*)d_in[5];
    const float* k_w     = (const float*)d_in[6];
    const float* v_w     = (const float*)d_in[7];
    const float* o_w     = (const float*)d_in[8];
    const float* norm_w  = (const float*)d_in[9];
    const float* gamma   = (const float*)d_in[10];
    float* out = (float*)d_out;

    cudaFuncSetAttribute(k4_oproj,
                         cudaFuncAttributeMaxDynamicSharedMemorySize, K4_SMEM);

    k0_prep<<<248, 256>>>(o_w, q_a_w, kv_a_w, q_b_w, k_w, v_w);
    k1_fused<<<NBLK, 256>>>(x, norm_w, q_bias, kv_bias);
    dim3 g3(TT/128, BB*HH);
    k3_attn_mma<<<g3, 128>>>();
    dim3 g4(NTOK/64, 4);
    k4_oproj<<<g4, 256, K4_SMEM>>>(x, gamma, out);
}

// round 16
// speedup vs baseline: 1.6331x; 1.1006x over previous
#include <cuda_runtime.h>
#include <cuda_bf16.h>
#include <cuda_fp16.h>
#include <cstdint>

#define BB 4
#define TT 2048
#define CC 256
#define HH 8
#define DH 32
#define QR 32
#define KVR 64
#define NTOK (BB*TT)          // 8192
#define TOKTILE 16
#define NBLK (NTOK/TOKTILE)   // 512

// ---------------- scratch (device globals; no allocation allowed) ----------------
__device__ __nv_bfloat16 g_qb[(size_t)BB*HH*TT*DH];      // [bh][t][d], pre-scaled, bf16
__device__ __nv_bfloat16 g_kb[(size_t)BB*HH*TT*DH];      // [bh][t][d], bf16
__device__ unsigned short g_vT[(size_t)BB*HH*DH*TT];     // [bh][d][t]  transposed, FP16 bits
__device__ unsigned g_yb[(size_t)NTOK*CC/2];             // attention out, bf16 pairs [tok][c/2]
__device__ unsigned g_owb[(size_t)256*128];              // o_w bf16 pairs [d][c2]
__device__ ulonglong2 g_wAT4[(size_t)64*96];             // down-proj W^T packed [c4][r]
__device__ unsigned g_wub[(size_t)768*32];               // up-proj weights bf16 pairs [n][r/2]

typedef unsigned long long u64;

// ---------------- packed f32x2 helpers ----------------
__device__ __forceinline__ u64 pack2(float lo, float hi) {
    u64 r; asm("mov.b64 %0, {%1, %2};" : "=l"(r) : "f"(lo), "f"(hi)); return r;
}
__device__ __forceinline__ float2 unpack2(u64 v) {
    float2 r; asm("mov.b64 {%0, %1}, %2;" : "=f"(r.x), "=f"(r.y) : "l"(v)); return r;
}
__device__ __forceinline__ u64 fma2(u64 a, u64 b, u64 c) {
    u64 d; asm("fma.rn.f32x2 %0, %1, %2, %3;" : "=l"(d) : "l"(a), "l"(b), "l"(c)); return d;
}

// ---------------- 16-bit helpers ----------------
__device__ __forceinline__ unsigned bf16x2(float lo, float hi) {
    unsigned r; asm("cvt.rn.bf16x2.f32 %0, %1, %2;" : "=r"(r) : "f"(hi), "f"(lo)); return r;
}
__device__ __forceinline__ unsigned f16x2(float lo, float hi) {
    unsigned r; asm("cvt.rn.f16x2.f32 %0, %1, %2;" : "=r"(r) : "f"(hi), "f"(lo)); return r;
}
// packed exp2 on two f16 lanes (one MUFU instruction for 2 values)
__device__ __forceinline__ unsigned ex2_f16x2(float lo, float hi) {
    unsigned t, r;
    asm("cvt.rn.f16x2.f32 %0, %1, %2;" : "=r"(t) : "f"(hi), "f"(lo));
    asm("ex2.approx.f16x2 %0, %1;" : "=r"(r) : "r"(t));
    return r;
}
__device__ __forceinline__ void mma_bf16(float* d,
    unsigned a0, unsigned a1, unsigned a2, unsigned a3, unsigned b0, unsigned b1) {
    asm volatile("mma.sync.aligned.m16n8k16.row.col.f32.bf16.bf16.f32 "
        "{%0,%1,%2,%3}, {%4,%5,%6,%7}, {%8,%9}, {%0,%1,%2,%3};"
        : "+f"(d[0]), "+f"(d[1]), "+f"(d[2]), "+f"(d[3])
        : "r"(a0), "r"(a1), "r"(a2), "r"(a3), "r"(b0), "r"(b1));
}
__device__ __forceinline__ void mma_f16(float* d,
    unsigned a0, unsigned a1, unsigned a2, unsigned a3, unsigned b0, unsigned b1) {
    asm volatile("mma.sync.aligned.m16n8k16.row.col.f32.f16.f16.f32 "
        "{%0,%1,%2,%3}, {%4,%5,%6,%7}, {%8,%9}, {%0,%1,%2,%3};"
        : "+f"(d[0]), "+f"(d[1]), "+f"(d[2]), "+f"(d[3])
        : "r"(a0), "r"(a1), "r"(a2), "r"(a3), "r"(b0), "r"(b1));
}

// ============================================================================
// k0: one-time weight repack/transpose.
// ============================================================================
__global__ void __launch_bounds__(256) k0_prep(
    const float* __restrict__ o_w,
    const float* __restrict__ q_a_w, const float* __restrict__ kv_a_w,
    const float* __restrict__ q_b_w, const float* __restrict__ k_w,
    const float* __restrict__ v_w)
{
    int i = blockIdx.x * 256 + threadIdx.x;
    if (i < 32768) {
        int d = i >> 7, c2 = i & 127;
        g_owb[(size_t)d*128 + c2] = bf16x2(o_w[(size_t)d*256 + 2*c2],
                                           o_w[(size_t)d*256 + 2*c2 + 1]);
    } else if (i < 38912) {
        int j = i - 32768;
        int c4 = j / 96, r = j % 96;
        const float* src = (r < QR) ? (q_a_w + (size_t)r*CC)
                                    : (kv_a_w + (size_t)(r-QR)*CC);
        ulonglong2 v;
        v.x = pack2(src[4*c4],     src[4*c4 + 1]);
        v.y = pack2(src[4*c4 + 2], src[4*c4 + 3]);
        g_wAT4[(size_t)c4*96 + r] = v;
    } else if (i < 63488) {
        int j = i - 38912;
        int n = j >> 5, cx = j & 31;
        float lo = 0.f, hi = 0.f;
        if (n < 256) {
            if (cx < 16) { lo = q_b_w[(size_t)n*QR + 2*cx]; hi = q_b_w[(size_t)n*QR + 2*cx + 1]; }
        } else if (n < 512) {
            lo = k_w[(size_t)(n-256)*KVR + 2*cx]; hi = k_w[(size_t)(n-256)*KVR + 2*cx + 1];
        } else {
            lo = v_w[(size_t)(n-512)*KVR + 2*cx]; hi = v_w[(size_t)(n-512)*KVR + 2*cx + 1];
        }
        g_wub[(size_t)n*32 + cx] = bf16x2(lo, hi);
    }
}

// ============================================================================
// k1: FUSED LayerNorm + down-proj (fp32 fma2) + up-proj (bf16 TENSOR MMA).
// q/k bf16; v FP16 (transposed via smem).
// ============================================================================
__global__ void __launch_bounds__(256) k1_fused(
    const float* __restrict__ x, const float* __restrict__ norm_w,
    const float* __restrict__ q_bias, const float* __restrict__ kv_bias)
{
    __shared__ __align__(16) float xs[TOKTILE][CC];
    __shared__ __align__(16) __nv_bfloat16 latb[16*104];   // [t][r], stride 104
    __shared__ __align__(16) __nv_bfloat16 vsb[16*264];    // [t][c], stride 264 (f16 bits)
    const int tok0 = blockIdx.x * TOKTILE;
    const int tid = threadIdx.x;

    const float4* xsrc = (const float4*)(x + (size_t)tok0 * CC);
    float4* xd = (float4*)xs;
#pragma unroll
    for (int i = 0; i < 4; i++) xd[tid + i*256] = xsrc[tid + i*256];
    __syncthreads();

    // LayerNorm
    const int w = tid >> 5, l = tid & 31;
    for (int t = w; t < TOKTILE; t += 8) {
        float s = 0.f, sq = 0.f;
#pragma unroll
        for (int i = 0; i < 8; i++) { float v = xs[t][l + 32*i]; s += v; sq += v*v; }
#pragma unroll
        for (int o = 16; o; o >>= 1) {
            s  += __shfl_xor_sync(0xffffffffu, s,  o);
            sq += __shfl_xor_sync(0xffffffffu, sq, o);
        }
        float mean = s * (1.f/CC);
        float var  = sq * (1.f/CC) - mean*mean;
        float rstd = 1.f / sqrtf(var + 1e-5f);
#pragma unroll
        for (int i = 0; i < 8; i++) {
            int c = l + 32*i;
            xs[t][c] = (xs[t][c] - mean) * rstd * norm_w[c];
        }
    }
    __syncthreads();

    // down-proj: 192 threads; write lat bf16 [t][r]
    if (tid < 192) {
        const int r = tid % 96, th = tid / 96;
        const int t0 = th * 8;
        u64 acc[8];
#pragma unroll
        for (int tt = 0; tt < 8; tt++) acc[tt] = 0ull;
#pragma unroll 8
        for (int c4 = 0; c4 < 64; c4++) {
            ulonglong2 w4 = g_wAT4[(size_t)c4*96 + r];
#pragma unroll
            for (int tt = 0; tt < 8; tt++) {
                ulonglong2 xv = *(const ulonglong2*)&xs[t0 + tt][4*c4];
                acc[tt] = fma2(xv.x, w4.x, acc[tt]);
                acc[tt] = fma2(xv.y, w4.y, acc[tt]);
            }
        }
        const float bias = (r < QR) ? q_bias[r] : kv_bias[r - QR];
#pragma unroll
        for (int tt = 0; tt < 8; tt++) {
            float2 a = unpack2(acc[tt]);
            latb[(t0 + tt)*104 + r] = __float2bfloat16_rn(a.x + a.y + bias);
        }
    }
    __syncthreads();

    // up-proj on tensor cores
    const int lane = tid & 31, gid = lane >> 2, tig = lane & 3;
    const float SC = 0.17677669529663687f * 1.4426950408889634f; // 1/sqrt(32)*log2(e)

    unsigned aA[6][4];
    const unsigned* latu = (const unsigned*)latb;
#pragma unroll
    for (int kg = 0; kg < 6; kg++) {
        aA[kg][0] = latu[gid*52 + 8*kg + tig];
        aA[kg][1] = latu[(gid+8)*52 + 8*kg + tig];
        aA[kg][2] = latu[gid*52 + 8*kg + tig + 4];
        aA[kg][3] = latu[(gid+8)*52 + 8*kg + tig + 4];
    }

    const int b = tok0 / TT;
    const int tA = (tok0 % TT) + gid;
    unsigned* gq_u = (unsigned*)g_qb;
    unsigned* gk_u = (unsigned*)g_kb;
    unsigned* vs_u = (unsigned*)vsb;

#pragma unroll
    for (int j = 0; j < 12; j++) {
        const int nc = w + 8*j;
        const int row = 8*nc + gid;
        float acc[4] = {0.f, 0.f, 0.f, 0.f};
        if (nc < 32) {
#pragma unroll
            for (int kk = 0; kk < 2; kk++) {
                unsigned b0 = g_wub[(size_t)row*32 + 8*kk + tig];
                unsigned b1 = g_wub[(size_t)row*32 + 8*kk + tig + 4];
                mma_bf16(acc, aA[kk][0], aA[kk][1], aA[kk][2], aA[kk][3], b0, b1);
            }
            int h = nc >> 2, d2 = 4*(nc & 3) + tig;
            size_t base = ((size_t)(b*HH + h)*TT + tA)*16 + d2;
            gq_u[base]       = bf16x2(acc[0]*SC, acc[1]*SC);
            gq_u[base + 128] = bf16x2(acc[2]*SC, acc[3]*SC);
        } else {
#pragma unroll
            for (int kk = 0; kk < 4; kk++) {
                unsigned b0 = g_wub[(size_t)row*32 + 8*kk + tig];
                unsigned b1 = g_wub[(size_t)row*32 + 8*kk + tig + 4];
                mma_bf16(acc, aA[2+kk][0], aA[2+kk][1], aA[2+kk][2], aA[2+kk][3], b0, b1);
            }
            if (nc < 64) {
                int ncl = nc - 32;
                int h = ncl >> 2, d2 = 4*(ncl & 3) + tig;
                size_t base = ((size_t)(b*HH + h)*TT + tA)*16 + d2;
                gk_u[base]       = bf16x2(acc[0], acc[1]);
                gk_u[base + 128] = bf16x2(acc[2], acc[3]);
            } else {
                int c2 = 4*(nc - 64) + tig;
                vs_u[gid*132 + c2]     = f16x2(acc[0], acc[1]);   // FP16 v
                vs_u[(gid+8)*132 + c2] = f16x2(acc[2], acc[3]);
            }
        }
    }
    __syncthreads();

    // v transpose store (raw 16-bit moves)
    {
        const int c = tid, h = c >> 5, d = c & 31;
        const unsigned short* vh = (const unsigned short*)vsb;
        unsigned* vt_u = (unsigned*)g_vT + (((size_t)(b*HH + h)*DH + d)*TT + (tok0 % TT))/2;
#pragma unroll
        for (int p = 0; p < 8; p++) {
            unsigned lo = vh[(2*p)*264 + c];
            unsigned hi = vh[(2*p+1)*264 + c];
            vt_u[p] = lo | (hi << 16);
        }
    }
}

// ============================================================================
// k3: flash attention. QK bf16 MMA; P via ex2.approx.f16x2 (packed exps);
// PV f16 MMA with a ones-column computing row sums in the fp32 accumulator.
// Double-buffered K/V tiles.
// ============================================================================
#define KB_STR 40
#define VB_STR 72
__global__ void __launch_bounds__(128, 3) k3_attn_mma()
{
    __shared__ __align__(16) __nv_bfloat16 Kbs[2][64*KB_STR];    // [buf][key][dim] bf16
    __shared__ __align__(16) unsigned short Vbs[2][40*VB_STR];   // [buf][dim][key] f16; rows 32..39 const

    const int tid = threadIdx.x;
    const int w = tid >> 5, lane = tid & 31;
    const int gid = lane >> 2, tig = lane & 3;
    const int bh = blockIdx.y;
    const int qbase = blockIdx.x * 128 + w * 32;

    const __nv_bfloat16* qptr = g_qb + (size_t)bh*TT*DH;
    unsigned qA[2][2][4];
#pragma unroll
    for (int mh = 0; mh < 2; mh++) {
        const int rA = qbase + 16*mh + gid, rB = rA + 8;
#pragma unroll
        for (int kg = 0; kg < 2; kg++) {
            qA[mh][kg][0] = *(const unsigned*)(qptr + (size_t)rA*DH + 16*kg + 2*tig);
            qA[mh][kg][1] = *(const unsigned*)(qptr + (size_t)rB*DH + 16*kg + 2*tig);
            qA[mh][kg][2] = *(const unsigned*)(qptr + (size_t)rA*DH + 16*kg + 2*tig + 8);
            qA[mh][kg][3] = *(const unsigned*)(qptr + (size_t)rB*DH + 16*kg + 2*tig + 8);
        }
    }

    float y[2][5][4];   // [mh][nc2 0..3 dims, 4 = row-sum chunk][frag]
#pragma unroll
    for (int mh = 0; mh < 2; mh++)
#pragma unroll
        for (int i = 0; i < 5; i++)
#pragma unroll
            for (int j = 0; j < 4; j++) y[mh][i][j] = 0.f;

    const uint2* kg2 = (const uint2*)(g_kb + (size_t)bh*TT*DH);
    const uint2* vg2 = (const uint2*)(g_vT + (size_t)bh*DH*TT);

    const int krow = tid >> 3, kc = tid & 7;      // K: 16 rows/pass, 8 uint2 cols
    const int vrow = tid >> 4, vc = tid & 15;     // V: 8 rows/pass, 16 uint2 cols

    // constant rows 32..39 of both V buffers: row 32 = f16 1.0, rows 33..39 = 0
    for (int i = tid; i < 2*8*(VB_STR/2); i += 128) {
        int buf = i / (8*(VB_STR/2));
        int rem = i % (8*(VB_STR/2));
        int r = rem / (VB_STR/2), c = rem % (VB_STR/2);
        unsigned val = (r == 0) ? 0x3C003C00u : 0u;
        ((unsigned*)&Vbs[buf][(32 + r)*VB_STR])[c] = val;
    }

    // prologue: load tile 0 into buffer 0
#pragma unroll
    for (int i = 0; i < 4; i++) {
        *(uint2*)((__nv_bfloat16*)&Kbs[0][0] + (krow + 16*i)*KB_STR + kc*4) = kg2[(size_t)(krow + 16*i)*8 + kc];
        *(uint2*)(&Vbs[0][0] + (vrow + 8*i)*VB_STR + vc*4) = vg2[(size_t)(vrow + 8*i)*(TT/4) + vc];
    }
    __syncthreads();

    for (int t = 0; t < TT/64; t++) {
        const int cur = t & 1;
        if (t + 1 < TT/64) {
            const int kt = (t + 1) * 64;
            __nv_bfloat16* kd = &Kbs[cur ^ 1][0];
            unsigned short* vd = &Vbs[cur ^ 1][0];
#pragma unroll
            for (int i = 0; i < 4; i++) {
                *(uint2*)(kd + (krow + 16*i)*KB_STR + kc*4) = kg2[(size_t)(kt + krow + 16*i)*8 + kc];
                *(uint2*)(vd + (vrow + 8*i)*VB_STR + vc*4)  = vg2[(size_t)(vrow + 8*i)*(TT/4) + kt/4 + vc];
            }
        }

        const __nv_bfloat16* Kc = &Kbs[cur][0];
        const unsigned short* Vc = &Vbs[cur][0];

#pragma unroll
        for (int sub = 0; sub < 2; sub++) {
            const int kb0 = 32*sub;

            float s[2][4][4];
#pragma unroll
            for (int nc = 0; nc < 4; nc++) {
                s[0][nc][0] = s[0][nc][1] = s[0][nc][2] = s[0][nc][3] = 0.f;
                s[1][nc][0] = s[1][nc][1] = s[1][nc][2] = s[1][nc][3] = 0.f;
#pragma unroll
                for (int kg = 0; kg < 2; kg++) {
                    const __nv_bfloat16* kr = Kc + (kb0 + 8*nc + gid)*KB_STR + 16*kg + 2*tig;
                    unsigned b0 = *(const unsigned*)(kr);
                    unsigned b1 = *(const unsigned*)(kr + 8);
                    mma_bf16(s[0][nc], qA[0][kg][0], qA[0][kg][1], qA[0][kg][2], qA[0][kg][3], b0, b1);
                    mma_bf16(s[1][nc], qA[1][kg][0], qA[1][kg][1], qA[1][kg][2], qA[1][kg][3], b0, b1);
                }
            }

            // packed exps: P directly as f16x2 A-frags (no sums, no separate cvts)
            unsigned pa[2][2][4];
#pragma unroll
            for (int mh = 0; mh < 2; mh++) {
#pragma unroll
                for (int kg = 0; kg < 2; kg++) {
                    pa[mh][kg][0] = ex2_f16x2(s[mh][2*kg][0],   s[mh][2*kg][1]);
                    pa[mh][kg][1] = ex2_f16x2(s[mh][2*kg][2],   s[mh][2*kg][3]);
                    pa[mh][kg][2] = ex2_f16x2(s[mh][2*kg+1][0], s[mh][2*kg+1][1]);
                    pa[mh][kg][3] = ex2_f16x2(s[mh][2*kg+1][2], s[mh][2*kg+1][3]);
                }
            }

            // Y += P V ; nc2 = 4 is the ones-column chunk -> row sums in fp32 acc
#pragma unroll
            for (int kg = 0; kg < 2; kg++) {
#pragma unroll
                for (int nc2 = 0; nc2 < 5; nc2++) {
                    const unsigned short* vr = Vc + (8*nc2 + gid)*VB_STR + kb0 + 16*kg + 2*tig;
                    unsigned b0 = *(const unsigned*)(vr);
                    unsigned b1 = *(const unsigned*)(vr + 8);
                    mma_f16(y[0][nc2], pa[0][kg][0], pa[0][kg][1], pa[0][kg][2], pa[0][kg][3], b0, b1);
                    mma_f16(y[1][nc2], pa[1][kg][0], pa[1][kg][1], pa[1][kg][2], pa[1][kg][3], b0, b1);
                }
            }
        }
        __syncthreads();
    }

    // row sums live in y[mh][4][0]/[2] of tig==0 threads (dim-32 column); broadcast.
    const int b = bh >> 3, h = bh & 7;
#pragma unroll
    for (int mh = 0; mh < 2; mh++) {
        float sA = __shfl_sync(0xffffffffu, y[mh][4][0], lane & 28);
        float sB = __shfl_sync(0xffffffffu, y[mh][4][2], lane & 28);
        const float inv0 = 1.0f / sA, inv1 = 1.0f / sB;
        const int rA = qbase + 16*mh + gid, rB = rA + 8;
#pragma unroll
        for (int nc2 = 0; nc2 < 4; nc2++) {
            int col = h*DH + nc2*8 + 2*tig;
            g_yb[((size_t)(b*TT + rA)*CC + col) >> 1] = bf16x2(y[mh][nc2][0]*inv0, y[mh][nc2][1]*inv0);
            g_yb[((size_t)(b*TT + rB)*CC + col) >> 1] = bf16x2(y[mh][nc2][2]*inv1, y[mh][nc2][3]*inv1);
        }
    }
}

// ============================================================================
// k4: output projection, bf16 MMA with SMEM-STAGED weights.
// ============================================================================
#define K4_SMEM (2*64*132*4)
__global__ void __launch_bounds__(256) k4_oproj(
    const float* __restrict__ x, const float* __restrict__ gamma,
    float* __restrict__ out)
{
    extern __shared__ __align__(16) unsigned k4s[];
    unsigned* ws = k4s;
    unsigned* ys = k4s + 64*132;
    const int tid = threadIdx.x;
    const int w = tid >> 5, lane = tid & 31;
    const int gid = lane >> 2, tig = lane & 3;
    const int tok0 = blockIdx.x * 64;
    const int cg = blockIdx.y;

    {
        const uint4* wsrc = (const uint4*)(g_owb + (size_t)(cg*64)*128);
        const uint4* ysrc = (const uint4*)(g_yb + (size_t)tok0*128);
        uint4* ws4 = (uint4*)ws;
        uint4* ys4 = (uint4*)ys;
#pragma unroll
        for (int i = 0; i < 8; i++) {
            int idx = tid + 256*i;
            int r = idx >> 5, c4 = idx & 31;
            ws4[r*33 + c4] = wsrc[r*32 + c4];
            ys4[r*33 + c4] = ysrc[r*32 + c4];
        }
    }
    __syncthreads();

    const __nv_bfloat16* wsh = (const __nv_bfloat16*)ws;
    const __nv_bfloat16* ysh = (const __nv_bfloat16*)ys;

    float acc[4][4];
#pragma unroll
    for (int m = 0; m < 4; m++)
#pragma unroll
        for (int j = 0; j < 4; j++) acc[m][j] = 0.f;

#pragma unroll 4
    for (int kg = 0; kg < 16; kg++) {
        const __nv_bfloat16* wr = wsh + (8*w + gid)*264 + 16*kg + 2*tig;
        unsigned b0 = *(const unsigned*)(wr);
        unsigned b1 = *(const unsigned*)(wr + 8);
#pragma unroll
        for (int m = 0; m < 4; m++) {
            const __nv_bfloat16* yr = ysh + (16*m + gid)*264 + 16*kg + 2*tig;
            unsigned a0 = *(const unsigned*)(yr);
            unsigned a1 = *(const unsigned*)(yr + 8*264);
            unsigned a2 = *(const unsigned*)(yr + 8);
            unsigned a3 = *(const unsigned*)(yr + 8*264 + 8);
            mma_bf16(acc[m], a0, a1, a2, a3, b0, b1);
        }
    }

    const int n = cg*64 + 8*w + 2*tig;
    const float g0 = gamma[n], g1 = gamma[n + 1];
#pragma unroll
    for (int m = 0; m < 4; m++) {
        int rA = tok0 + 16*m + gid, rB = rA + 8;
        float2 xA = *(const float2*)&x[(size_t)rA*CC + n];
        float2 xB = *(const float2*)&x[(size_t)rB*CC + n];
        float2 oA; oA.x = xA.x + g0*acc[m][0]; oA.y = xA.y + g1*acc[m][1];
        float2 oB; oB.x = xB.x + g0*acc[m][2]; oB.y = xB.y + g1*acc[m][3];
        *(float2*)&out[(size_t)rA*CC + n] = oA;
        *(float2*)&out[(size_t)rB*CC + n] = oB;
    }
}

// ============================================================================
extern "C" void kernel_launch(void* const* d_in, const int* in_sizes, int n_in,
                              void* d_out, int out_size)
{
    const float* x       = (const float*)d_in[0];
    const float* q_a_w   = (const float*)d_in[1];
    const float* q_bias  = (const float*)d_in[2];
    const float* q_b_w   = (const float*)d_in[3];
    const float* kv_a_w  = (const float*)d_in[4];
    const float* kv_bias = (const float*)d_in[5];
    const float* k_w     = (const float*)d_in[6];
    const float* v_w     = (const float*)d_in[7];
    const float* o_w     = (const float*)d_in[8];
    const float* norm_w  = (const float*)d_in[9];
    const float* gamma   = (const float*)d_in[10];
    float* out = (float*)d_out;

    cudaFuncSetAttribute(k4_oproj,
                         cudaFuncAttributeMaxDynamicSharedMemorySize, K4_SMEM);

    k0_prep<<<248, 256>>>(o_w, q_a_w, kv_a_w, q_b_w, k_w, v_w);
    k1_fused<<<NBLK, 256>>>(x, norm_w, q_bias, kv_bias);
    dim3 g3(TT/128, BB*HH);
    k3_attn_mma<<<g3, 128>>>();
    dim3 g4(NTOK/64, 4);
    k4_oproj<<<g4, 256, K4_SMEM>>>(x, gamma, out);
}

// round 17
// speedup vs baseline: 1.7986x; 1.1013x over previous
#include <cuda_runtime.h>
#include <cuda_bf16.h>
#include <cuda_fp16.h>
#include <cstdint>

#define BB 4
#define TT 2048
#define CC 256
#define HH 8
#define DH 32
#define QR 32
#define KVR 64
#define NTOK (BB*TT)          // 8192
#define TOKTILE 16
#define NBLK (NTOK/TOKTILE)   // 512

// ---------------- scratch (device globals; no allocation allowed) ----------------
__device__ __nv_bfloat16 g_qb[(size_t)BB*HH*TT*DH];      // [bh][t][d], pre-scaled, bf16
__device__ __nv_bfloat16 g_kb[(size_t)BB*HH*TT*DH];      // [bh][t][d], bf16
__device__ unsigned short g_vT[(size_t)BB*HH*DH*TT];     // [bh][d][t]  transposed, FP16 bits
__device__ unsigned g_yb[(size_t)NTOK*CC/2];             // attention out, bf16 pairs [tok][c/2]
__device__ unsigned g_owb[(size_t)256*128];              // o_w bf16 pairs [d][c2]
__device__ unsigned g_wAb[(size_t)96*128];               // down-proj weights bf16 pairs [r][c2]
__device__ unsigned g_wub[(size_t)768*32];               // up-proj weights bf16 pairs [n][r/2]

typedef unsigned long long u64;

// ---------------- 16-bit helpers ----------------
__device__ __forceinline__ unsigned bf16x2(float lo, float hi) {
    unsigned r; asm("cvt.rn.bf16x2.f32 %0, %1, %2;" : "=r"(r) : "f"(hi), "f"(lo)); return r;
}
__device__ __forceinline__ unsigned f16x2(float lo, float hi) {
    unsigned r; asm("cvt.rn.f16x2.f32 %0, %1, %2;" : "=r"(r) : "f"(hi), "f"(lo)); return r;
}
// packed exp2 on two f16 lanes (one MUFU instruction for 2 values)
__device__ __forceinline__ unsigned ex2_f16x2(float lo, float hi) {
    unsigned t, r;
    asm("cvt.rn.f16x2.f32 %0, %1, %2;" : "=r"(t) : "f"(hi), "f"(lo));
    asm("ex2.approx.f16x2 %0, %1;" : "=r"(r) : "r"(t));
    return r;
}
__device__ __forceinline__ void mma_bf16(float* d,
    unsigned a0, unsigned a1, unsigned a2, unsigned a3, unsigned b0, unsigned b1) {
    asm volatile("mma.sync.aligned.m16n8k16.row.col.f32.bf16.bf16.f32 "
        "{%0,%1,%2,%3}, {%4,%5,%6,%7}, {%8,%9}, {%0,%1,%2,%3};"
        : "+f"(d[0]), "+f"(d[1]), "+f"(d[2]), "+f"(d[3])
        : "r"(a0), "r"(a1), "r"(a2), "r"(a3), "r"(b0), "r"(b1));
}
__device__ __forceinline__ void mma_f16(float* d,
    unsigned a0, unsigned a1, unsigned a2, unsigned a3, unsigned b0, unsigned b1) {
    asm volatile("mma.sync.aligned.m16n8k16.row.col.f32.f16.f16.f32 "
        "{%0,%1,%2,%3}, {%4,%5,%6,%7}, {%8,%9}, {%0,%1,%2,%3};"
        : "+f"(d[0]), "+f"(d[1]), "+f"(d[2]), "+f"(d[3])
        : "r"(a0), "r"(a1), "r"(a2), "r"(a3), "r"(b0), "r"(b1));
}

// ============================================================================
// k0: one-time weight repack/transpose.
// ranges: [0,32768) owb | [32768,45056) wAb | [45056,69632) wub
// ============================================================================
__global__ void __launch_bounds__(256) k0_prep(
    const float* __restrict__ o_w,
    const float* __restrict__ q_a_w, const float* __restrict__ kv_a_w,
    const float* __restrict__ q_b_w, const float* __restrict__ k_w,
    const float* __restrict__ v_w)
{
    int i = blockIdx.x * 256 + threadIdx.x;
    if (i < 32768) {
        int d = i >> 7, c2 = i & 127;
        g_owb[(size_t)d*128 + c2] = bf16x2(o_w[(size_t)d*256 + 2*c2],
                                           o_w[(size_t)d*256 + 2*c2 + 1]);
    } else if (i < 45056) {
        int j = i - 32768;            // 0..12287
        int r = j >> 7, c2 = j & 127;
        const float* src = (r < QR) ? (q_a_w + (size_t)r*CC)
                                    : (kv_a_w + (size_t)(r-QR)*CC);
        g_wAb[(size_t)r*128 + c2] = bf16x2(src[2*c2], src[2*c2 + 1]);
    } else if (i < 69632) {
        int j = i - 45056;
        int n = j >> 5, cx = j & 31;
        float lo = 0.f, hi = 0.f;
        if (n < 256) {
            if (cx < 16) { lo = q_b_w[(size_t)n*QR + 2*cx]; hi = q_b_w[(size_t)n*QR + 2*cx + 1]; }
        } else if (n < 512) {
            lo = k_w[(size_t)(n-256)*KVR + 2*cx]; hi = k_w[(size_t)(n-256)*KVR + 2*cx + 1];
        } else {
            lo = v_w[(size_t)(n-512)*KVR + 2*cx]; hi = v_w[(size_t)(n-512)*KVR + 2*cx + 1];
        }
        g_wub[(size_t)n*32 + cx] = bf16x2(lo, hi);
    }
}

// ============================================================================
// k1: FUSED LayerNorm + down-proj (bf16 MMA) + up-proj (bf16 MMA).
// q/k bf16; v FP16 (transposed via smem).
// ============================================================================
__global__ void __launch_bounds__(256) k1_fused(
    const float* __restrict__ x, const float* __restrict__ norm_w,
    const float* __restrict__ q_bias, const float* __restrict__ kv_bias)
{
    __shared__ __align__(16) float xs[TOKTILE][CC];
    __shared__ __align__(16) unsigned xbu[16*132];         // normalized x bf16 pairs, stride 132
    __shared__ __align__(16) __nv_bfloat16 latb[16*104];   // [t][r], stride 104
    __shared__ __align__(16) __nv_bfloat16 vsb[16*264];    // [t][c], stride 264 (f16 bits)
    const int tok0 = blockIdx.x * TOKTILE;
    const int tid = threadIdx.x;
    const int w = tid >> 5, lane = tid & 31;
    const int gid = lane >> 2, tig = lane & 3;

    const float4* xsrc = (const float4*)(x + (size_t)tok0 * CC);
    float4* xd = (float4*)xs;
#pragma unroll
    for (int i = 0; i < 4; i++) xd[tid + i*256] = xsrc[tid + i*256];
    __syncthreads();

    // LayerNorm (warp per token, 2 tokens per warp)
    const int l = lane;
    for (int t = w; t < TOKTILE; t += 8) {
        float s = 0.f, sq = 0.f;
#pragma unroll
        for (int i = 0; i < 8; i++) { float v = xs[t][l + 32*i]; s += v; sq += v*v; }
#pragma unroll
        for (int o = 16; o; o >>= 1) {
            s  += __shfl_xor_sync(0xffffffffu, s,  o);
            sq += __shfl_xor_sync(0xffffffffu, sq, o);
        }
        float mean = s * (1.f/CC);
        float var  = sq * (1.f/CC) - mean*mean;
        float rstd = 1.f / sqrtf(var + 1e-5f);
#pragma unroll
        for (int i = 0; i < 8; i++) {
            int c = l + 32*i;
            xs[t][c] = (xs[t][c] - mean) * rstd * norm_w[c];
        }
    }
    __syncthreads();

    // pack normalized x to bf16 pairs (A-frag layout, conflict-free stride 132)
    {
        const int t = tid >> 4, j0 = (tid & 15) * 8;
#pragma unroll
        for (int j = 0; j < 8; j++) {
            int c2 = j0 + j;
            xbu[t*132 + c2] = bf16x2(xs[t][2*c2], xs[t][2*c2 + 1]);
        }
    }
    __syncthreads();

    // down-proj on tensor cores: warps 0..5, each 2 rank-chunks (nc = 2w, 2w+1)
    if (w < 6) {
        float acc[2][4];
        acc[0][0]=acc[0][1]=acc[0][2]=acc[0][3]=0.f;
        acc[1][0]=acc[1][1]=acc[1][2]=acc[1][3]=0.f;
#pragma unroll 4
        for (int kg = 0; kg < 16; kg++) {
            unsigned a0 = xbu[gid*132 + 8*kg + tig];
            unsigned a1 = xbu[(gid+8)*132 + 8*kg + tig];
            unsigned a2 = xbu[gid*132 + 8*kg + tig + 4];
            unsigned a3 = xbu[(gid+8)*132 + 8*kg + tig + 4];
#pragma unroll
            for (int q = 0; q < 2; q++) {
                int nc = 2*w + q;
                unsigned b0 = g_wAb[(size_t)(8*nc + gid)*128 + 8*kg + tig];
                unsigned b1 = g_wAb[(size_t)(8*nc + gid)*128 + 8*kg + tig + 4];
                mma_bf16(acc[q], a0, a1, a2, a3, b0, b1);
            }
        }
        unsigned* latp = (unsigned*)latb;
#pragma unroll
        for (int q = 0; q < 2; q++) {
            int nc = 2*w + q;
            int r = 8*nc + 2*tig;
            float bias0 = (r < QR) ? q_bias[r]     : kv_bias[r - QR];
            float bias1 = (r < QR) ? q_bias[r + 1] : kv_bias[r + 1 - QR];
            latp[gid*52 + 4*nc + tig]     = bf16x2(acc[q][0] + bias0, acc[q][1] + bias1);
            latp[(gid+8)*52 + 4*nc + tig] = bf16x2(acc[q][2] + bias0, acc[q][3] + bias1);
        }
    }
    __syncthreads();

    // up-proj on tensor cores
    const float SC = 0.17677669529663687f * 1.4426950408889634f; // 1/sqrt(32)*log2(e)

    unsigned aA[6][4];
    const unsigned* latu = (const unsigned*)latb;
#pragma unroll
    for (int kg = 0; kg < 6; kg++) {
        aA[kg][0] = latu[gid*52 + 8*kg + tig];
        aA[kg][1] = latu[(gid+8)*52 + 8*kg + tig];
        aA[kg][2] = latu[gid*52 + 8*kg + tig + 4];
        aA[kg][3] = latu[(gid+8)*52 + 8*kg + tig + 4];
    }

    const int b = tok0 / TT;
    const int tA = (tok0 % TT) + gid;
    unsigned* gq_u = (unsigned*)g_qb;
    unsigned* gk_u = (unsigned*)g_kb;
    unsigned* vs_u = (unsigned*)vsb;

#pragma unroll
    for (int j = 0; j < 12; j++) {
        const int nc = w + 8*j;
        const int row = 8*nc + gid;
        float acc[4] = {0.f, 0.f, 0.f, 0.f};
        if (nc < 32) {
#pragma unroll
            for (int kk = 0; kk < 2; kk++) {
                unsigned b0 = g_wub[(size_t)row*32 + 8*kk + tig];
                unsigned b1 = g_wub[(size_t)row*32 + 8*kk + tig + 4];
                mma_bf16(acc, aA[kk][0], aA[kk][1], aA[kk][2], aA[kk][3], b0, b1);
            }
            int h = nc >> 2, d2 = 4*(nc & 3) + tig;
            size_t base = ((size_t)(b*HH + h)*TT + tA)*16 + d2;
            gq_u[base]       = bf16x2(acc[0]*SC, acc[1]*SC);
            gq_u[base + 128] = bf16x2(acc[2]*SC, acc[3]*SC);
        } else {
#pragma unroll
            for (int kk = 0; kk < 4; kk++) {
                unsigned b0 = g_wub[(size_t)row*32 + 8*kk + tig];
                unsigned b1 = g_wub[(size_t)row*32 + 8*kk + tig + 4];
                mma_bf16(acc, aA[2+kk][0], aA[2+kk][1], aA[2+kk][2], aA[2+kk][3], b0, b1);
            }
            if (nc < 64) {
                int ncl = nc - 32;
                int h = ncl >> 2, d2 = 4*(ncl & 3) + tig;
                size_t base = ((size_t)(b*HH + h)*TT + tA)*16 + d2;
                gk_u[base]       = bf16x2(acc[0], acc[1]);
                gk_u[base + 128] = bf16x2(acc[2], acc[3]);
            } else {
                int c2 = 4*(nc - 64) + tig;
                vs_u[gid*132 + c2]     = f16x2(acc[0], acc[1]);   // FP16 v
                vs_u[(gid+8)*132 + c2] = f16x2(acc[2], acc[3]);
            }
        }
    }
    __syncthreads();

    // v transpose store (raw 16-bit moves)
    {
        const int c = tid, h = c >> 5, d = c & 31;
        const unsigned short* vh = (const unsigned short*)vsb;
        unsigned* vt_u = (unsigned*)g_vT + (((size_t)(b*HH + h)*DH + d)*TT + (tok0 % TT))/2;
#pragma unroll
        for (int p = 0; p < 8; p++) {
            unsigned lo = vh[(2*p)*264 + c];
            unsigned hi = vh[(2*p+1)*264 + c];
            vt_u[p] = lo | (hi << 16);
        }
    }
}

// ============================================================================
// k3: flash attention. QK bf16 MMA; P via ex2.approx.f16x2 (packed exps);
// PV f16 MMA with a ones-column computing row sums in the fp32 accumulator.
// Double-buffered K/V tiles.
// ============================================================================
#define KB_STR 40
#define VB_STR 72
__global__ void __launch_bounds__(128, 3) k3_attn_mma()
{
    __shared__ __align__(16) __nv_bfloat16 Kbs[2][64*KB_STR];    // [buf][key][dim] bf16
    __shared__ __align__(16) unsigned short Vbs[2][40*VB_STR];   // [buf][dim][key] f16; rows 32..39 const

    const int tid = threadIdx.x;
    const int w = tid >> 5, lane = tid & 31;
    const int gid = lane >> 2, tig = lane & 3;
    const int bh = blockIdx.y;
    const int qbase = blockIdx.x * 128 + w * 32;

    const __nv_bfloat16* qptr = g_qb + (size_t)bh*TT*DH;
    unsigned qA[2][2][4];
#pragma unroll
    for (int mh = 0; mh < 2; mh++) {
        const int rA = qbase + 16*mh + gid, rB = rA + 8;
#pragma unroll
        for (int kg = 0; kg < 2; kg++) {
            qA[mh][kg][0] = *(const unsigned*)(qptr + (size_t)rA*DH + 16*kg + 2*tig);
            qA[mh][kg][1] = *(const unsigned*)(qptr + (size_t)rB*DH + 16*kg + 2*tig);
            qA[mh][kg][2] = *(const unsigned*)(qptr + (size_t)rA*DH + 16*kg + 2*tig + 8);
            qA[mh][kg][3] = *(const unsigned*)(qptr + (size_t)rB*DH + 16*kg + 2*tig + 8);
        }
    }

    float y[2][5][4];   // [mh][nc2 0..3 dims, 4 = row-sum chunk][frag]
#pragma unroll
    for (int mh = 0; mh < 2; mh++)
#pragma unroll
        for (int i = 0; i < 5; i++)
#pragma unroll
            for (int j = 0; j < 4; j++) y[mh][i][j] = 0.f;

    const uint2* kg2 = (const uint2*)(g_kb + (size_t)bh*TT*DH);
    const uint2* vg2 = (const uint2*)(g_vT + (size_t)bh*DH*TT);

    const int krow = tid >> 3, kc = tid & 7;      // K: 16 rows/pass, 8 uint2 cols
    const int vrow = tid >> 4, vc = tid & 15;     // V: 8 rows/pass, 16 uint2 cols

    // constant rows 32..39 of both V buffers: row 32 = f16 1.0, rows 33..39 = 0
    for (int i = tid; i < 2*8*(VB_STR/2); i += 128) {
        int buf = i / (8*(VB_STR/2));
        int rem = i % (8*(VB_STR/2));
        int r = rem / (VB_STR/2), c = rem % (VB_STR/2);
        unsigned val = (r == 0) ? 0x3C003C00u : 0u;
        ((unsigned*)&Vbs[buf][(32 + r)*VB_STR])[c] = val;
    }

    // prologue: load tile 0 into buffer 0
#pragma unroll
    for (int i = 0; i < 4; i++) {
        *(uint2*)((__nv_bfloat16*)&Kbs[0][0] + (krow + 16*i)*KB_STR + kc*4) = kg2[(size_t)(krow + 16*i)*8 + kc];
        *(uint2*)(&Vbs[0][0] + (vrow + 8*i)*VB_STR + vc*4) = vg2[(size_t)(vrow + 8*i)*(TT/4) + vc];
    }
    __syncthreads();

    for (int t = 0; t < TT/64; t++) {
        const int cur = t & 1;
        if (t + 1 < TT/64) {
            const int kt = (t + 1) * 64;
            __nv_bfloat16* kd = &Kbs[cur ^ 1][0];
            unsigned short* vd = &Vbs[cur ^ 1][0];
#pragma unroll
            for (int i = 0; i < 4; i++) {
                *(uint2*)(kd + (krow + 16*i)*KB_STR + kc*4) = kg2[(size_t)(kt + krow + 16*i)*8 + kc];
                *(uint2*)(vd + (vrow + 8*i)*VB_STR + vc*4)  = vg2[(size_t)(vrow + 8*i)*(TT/4) + kt/4 + vc];
            }
        }

        const __nv_bfloat16* Kc = &Kbs[cur][0];
        const unsigned short* Vc = &Vbs[cur][0];

#pragma unroll
        for (int sub = 0; sub < 2; sub++) {
            const int kb0 = 32*sub;

            float s[2][4][4];
#pragma unroll
            for (int nc = 0; nc < 4; nc++) {
                s[0][nc][0] = s[0][nc][1] = s[0][nc][2] = s[0][nc][3] = 0.f;
                s[1][nc][0] = s[1][nc][1] = s[1][nc][2] = s[1][nc][3] = 0.f;
#pragma unroll
                for (int kg = 0; kg < 2; kg++) {
                    const __nv_bfloat16* kr = Kc + (kb0 + 8*nc + gid)*KB_STR + 16*kg + 2*tig;
                    unsigned b0 = *(const unsigned*)(kr);
                    unsigned b1 = *(const unsigned*)(kr + 8);
                    mma_bf16(s[0][nc], qA[0][kg][0], qA[0][kg][1], qA[0][kg][2], qA[0][kg][3], b0, b1);
                    mma_bf16(s[1][nc], qA[1][kg][0], qA[1][kg][1], qA[1][kg][2], qA[1][kg][3], b0, b1);
                }
            }

            // packed exps: P directly as f16x2 A-frags
            unsigned pa[2][2][4];
#pragma unroll
            for (int mh = 0; mh < 2; mh++) {
#pragma unroll
                for (int kg = 0; kg < 2; kg++) {
                    pa[mh][kg][0] = ex2_f16x2(s[mh][2*kg][0],   s[mh][2*kg][1]);
                    pa[mh][kg][1] = ex2_f16x2(s[mh][2*kg][2],   s[mh][2*kg][3]);
                    pa[mh][kg][2] = ex2_f16x2(s[mh][2*kg+1][0], s[mh][2*kg+1][1]);
                    pa[mh][kg][3] = ex2_f16x2(s[mh][2*kg+1][2], s[mh][2*kg+1][3]);
                }
            }

            // Y += P V ; nc2 = 4 is the ones-column chunk -> row sums in fp32 acc
#pragma unroll
            for (int kg = 0; kg < 2; kg++) {
#pragma unroll
                for (int nc2 = 0; nc2 < 5; nc2++) {
                    const unsigned short* vr = Vc + (8*nc2 + gid)*VB_STR + kb0 + 16*kg + 2*tig;
                    unsigned b0 = *(const unsigned*)(vr);
                    unsigned b1 = *(const unsigned*)(vr + 8);
                    mma_f16(y[0][nc2], pa[0][kg][0], pa[0][kg][1], pa[0][kg][2], pa[0][kg][3], b0, b1);
                    mma_f16(y[1][nc2], pa[1][kg][0], pa[1][kg][1], pa[1][kg][2], pa[1][kg][3], b0, b1);
                }
            }
        }
        __syncthreads();
    }

    // row sums live in y[mh][4][0]/[2] of tig==0 threads (dim-32 column); broadcast.
    const int b = bh >> 3, h = bh & 7;
#pragma unroll
    for (int mh = 0; mh < 2; mh++) {
        float sA = __shfl_sync(0xffffffffu, y[mh][4][0], lane & 28);
        float sB = __shfl_sync(0xffffffffu, y[mh][4][2], lane & 28);
        const float inv0 = 1.0f / sA, inv1 = 1.0f / sB;
        const int rA = qbase + 16*mh + gid, rB = rA + 8;
#pragma unroll
        for (int nc2 = 0; nc2 < 4; nc2++) {
            int col = h*DH + nc2*8 + 2*tig;
            g_yb[((size_t)(b*TT + rA)*CC + col) >> 1] = bf16x2(y[mh][nc2][0]*inv0, y[mh][nc2][1]*inv0);
            g_yb[((size_t)(b*TT + rB)*CC + col) >> 1] = bf16x2(y[mh][nc2][2]*inv1, y[mh][nc2][3]*inv1);
        }
    }
}

// ============================================================================
// k4: output projection, bf16 MMA with SMEM-STAGED weights.
// ============================================================================
#define K4_SMEM (2*64*132*4)
__global__ void __launch_bounds__(256) k4_oproj(
    const float* __restrict__ x, const float* __restrict__ gamma,
    float* __restrict__ out)
{
    extern __shared__ __align__(16) unsigned k4s[];
    unsigned* ws = k4s;
    unsigned* ys = k4s + 64*132;
    const int tid = threadIdx.x;
    const int w = tid >> 5, lane = tid & 31;
    const int gid = lane >> 2, tig = lane & 3;
    const int tok0 = blockIdx.x * 64;
    const int cg = blockIdx.y;

    {
        const uint4* wsrc = (const uint4*)(g_owb + (size_t)(cg*64)*128);
        const uint4* ysrc = (const uint4*)(g_yb + (size_t)tok0*128);
        uint4* ws4 = (uint4*)ws;
        uint4* ys4 = (uint4*)ys;
#pragma unroll
        for (int i = 0; i < 8; i++) {
            int idx = tid + 256*i;
            int r = idx >> 5, c4 = idx & 31;
            ws4[r*33 + c4] = wsrc[r*32 + c4];
            ys4[r*33 + c4] = ysrc[r*32 + c4];
        }
    }
    __syncthreads();

    const __nv_bfloat16* wsh = (const __nv_bfloat16*)ws;
    const __nv_bfloat16* ysh = (const __nv_bfloat16*)ys;

    float acc[4][4];
#pragma unroll
    for (int m = 0; m < 4; m++)
#pragma unroll
        for (int j = 0; j < 4; j++) acc[m][j] = 0.f;

#pragma unroll 4
    for (int kg = 0; kg < 16; kg++) {
        const __nv_bfloat16* wr = wsh + (8*w + gid)*264 + 16*kg + 2*tig;
        unsigned b0 = *(const unsigned*)(wr);
        unsigned b1 = *(const unsigned*)(wr + 8);
#pragma unroll
        for (int m = 0; m < 4; m++) {
            const __nv_bfloat16* yr = ysh + (16*m + gid)*264 + 16*kg + 2*tig;
            unsigned a0 = *(const unsigned*)(yr);
            unsigned a1 = *(const unsigned*)(yr + 8*264);
            unsigned a2 = *(const unsigned*)(yr + 8);
            unsigned a3 = *(const unsigned*)(yr + 8*264 + 8);
            mma_bf16(acc[m], a0, a1, a2, a3, b0, b1);
        }
    }

    const int n = cg*64 + 8*w + 2*tig;
    const float g0 = gamma[n], g1 = gamma[n + 1];
#pragma unroll
    for (int m = 0; m < 4; m++) {
        int rA = tok0 + 16*m + gid, rB = rA + 8;
        float2 xA = *(const float2*)&x[(size_t)rA*CC + n];
        float2 xB = *(const float2*)&x[(size_t)rB*CC + n];
        float2 oA; oA.x = xA.x + g0*acc[m][0]; oA.y = xA.y + g1*acc[m][1];
        float2 oB; oB.x = xB.x + g0*acc[m][2]; oB.y = xB.y + g1*acc[m][3];
        *(float2*)&out[(size_t)rA*CC + n] = oA;
        *(float2*)&out[(size_t)rB*CC + n] = oB;
    }
}

// ============================================================================
extern "C" void kernel_launch(void* const* d_in, const int* in_sizes, int n_in,
                              void* d_out, int out_size)
{
    const float* x       = (const float*)d_in[0];
    const float* q_a_w   = (const float*)d_in[1];
    const float* q_bias  = (const float*)d_in[2];
    const float* q_b_w   = (const float*)d_in[3];
    const float* kv_a_w  = (const float*)d_in[4];
    const float* kv_bias = (const float*)d_in[5];
    const float* k_w     = (const float*)d_in[6];
    const float* v_w     = (const float*)d_in[7];
    const float* o_w     = (const float*)d_in[8];
    const float* norm_w  = (const float*)d_in[9];
    const float* gamma   = (const float*)d_in[10];
    float* out = (float*)d_out;

    cudaFuncSetAttribute(k4_oproj,
                         cudaFuncAttributeMaxDynamicSharedMemorySize, K4_SMEM);

    k0_prep<<<272, 256>>>(o_w, q_a_w, kv_a_w, q_b_w, k_w, v_w);
    k1_fused<<<NBLK, 256>>>(x, norm_w, q_bias, kv_bias);
    dim3 g3(TT/128, BB*HH);
    k3_attn_mma<<<g3, 128>>>();
    dim3 g4(NTOK/64, 4);
    k4_oproj<<<g4, 256, K4_SMEM>>>(x, gamma, out);
}